// round 7
// baseline (speedup 1.0000x reference)
#include <cuda_runtime.h>
#include <cuda_fp16.h>
#include <cstdint>

#define K_DIM 4096
#define N_DIM 11008
#define GROUP 128
#define M_MAX 8192

#define TILE_M 128
#define TILE_N 128
#define KCHUNK 64                       // halves per K-chunk (128 bytes = SW128 row)
#define NKC (K_DIM / KCHUNK)            // 64 K-chunks
#define STAGES 4
#define NTHREADS 512

#define A_BLK_BYTES (TILE_M * 128)      // 16384
#define B_BLK_BYTES (TILE_N * 128)      // 16384

#define N_TILES (N_DIM / TILE_N)        // 86
#define M_TILES_MAX (M_MAX / TILE_M)    // 64

// Scratch: pre-tiled, pre-SW128-swizzled operands (device globals = sanctioned scratch)
__device__ unsigned char g_At[(size_t)M_TILES_MAX * NKC * A_BLK_BYTES]; // 64 MB
__device__ unsigned char g_Bt[(size_t)N_TILES   * NKC * B_BLK_BYTES];   // 90 MB

__device__ __forceinline__ uint32_t swz(uint32_t off) {          // SW128 swizzle
    return off ^ ((off >> 3) & 0x70);
}

__device__ __forceinline__ uint32_t smem_u32(const void* p) {
    uint32_t a;
    asm("{ .reg .u64 t; cvta.to.shared.u64 t, %1; cvt.u32.u64 %0, t; }" : "=r"(a) : "l"(p));
    return a;
}
__device__ __forceinline__ void cp_async16(uint32_t smem_dst, const void* gptr) {
    asm volatile("cp.async.cg.shared.global [%0], [%1], 16;\n" :: "r"(smem_dst), "l"(gptr));
}
__device__ __forceinline__ void cp_commit() {
    asm volatile("cp.async.commit_group;\n");
}
template <int Nn>
__device__ __forceinline__ void cp_wait() {
    asm volatile("cp.async.wait_group %0;\n" :: "n"(Nn));
}

// ---------------------------------------------------------------------------
// Kernel 0: convert x f32 -> f16, tiled + swizzled into g_At
// ---------------------------------------------------------------------------
__global__ void convert_a_kernel(const float* __restrict__ x, int M) {
    size_t idx = (size_t)blockIdx.x * blockDim.x + threadIdx.x;
    int k8 = (int)(idx & (K_DIM / 8 - 1));            // 0..511
    int m = (int)(idx >> 9);
    if (m >= M) return;
    const float4* src = reinterpret_cast<const float4*>(x + (size_t)m * K_DIM + k8 * 8);
    float4 v0 = src[0], v1 = src[1];
    __half2 h0 = __floats2half2_rn(v0.x, v0.y);
    __half2 h1 = __floats2half2_rn(v0.z, v0.w);
    __half2 h2 = __floats2half2_rn(v1.x, v1.y);
    __half2 h3 = __floats2half2_rn(v1.z, v1.w);
    uint4 pack;
    pack.x = *reinterpret_cast<uint32_t*>(&h0);
    pack.y = *reinterpret_cast<uint32_t*>(&h1);
    pack.z = *reinterpret_cast<uint32_t*>(&h2);
    pack.w = *reinterpret_cast<uint32_t*>(&h3);
    int k0 = k8 * 8;
    int mt = m >> 7, r = m & 127, kc = k0 >> 6, c0 = k0 & 63;
    size_t off = ((size_t)mt * NKC + kc) * A_BLK_BYTES + swz((uint32_t)(r * 128 + c0 * 2));
    *reinterpret_cast<uint4*>(g_At + off) = pack;
}

// ---------------------------------------------------------------------------
// Kernel 1: GPTQ int4 dequant -> f16 W^T [N,K], tiled + swizzled into g_Bt
// ---------------------------------------------------------------------------
__global__ void dequant_kernel(const int* __restrict__ qweight,
                               const int* __restrict__ qzeros,
                               const float* __restrict__ scales) {
    int n = blockIdx.x * blockDim.x + threadIdx.x;
    int i = blockIdx.y;                               // 0..K/8-1
    if (n >= N_DIM) return;

    int q = qweight[(size_t)i * N_DIM + n];
    int k0 = i * 8;
    int g = i >> 4;                                   // k0 / GROUP
    int zpack = qzeros[g * (N_DIM / 8) + (n >> 3)];
    float zf = (float)(((zpack >> ((n & 7) * 4)) & 15) + 1);
    float s = scales[(size_t)g * N_DIM + n];

    union { __half h[8]; uint4 v; } u;                // 16B-aligned pack
#pragma unroll
    for (int j = 0; j < 8; ++j)
        u.h[j] = __float2half(((float)((q >> (4 * j)) & 15) - zf) * s);

    int nt = n >> 7, r = n & 127, kc = k0 >> 6, c0 = k0 & 63;
    size_t off = ((size_t)nt * NKC + kc) * B_BLK_BYTES + swz((uint32_t)(r * 128 + c0 * 2));
    *reinterpret_cast<uint4*>(g_Bt + off) = u.v;
}

// ---------------------------------------------------------------------------
// Kernel 2: mma.sync GEMM  C[M,N] = A * B^T + bias  (f32 out)
// 512 threads, 16 warps (4x4), each warp 32(M) x 32(N).
// 4-stage cp.async pipeline, one __syncthreads per K-chunk.
// ---------------------------------------------------------------------------
#define SM_BIAS   0                                  // 128 f32
#define SM_A      1024                               // 4 x 16KB
#define SM_B      (SM_A + STAGES * A_BLK_BYTES)
#define SM_TOTAL  (SM_B + STAGES * B_BLK_BYTES)      // 132096 B

__global__ void __launch_bounds__(NTHREADS, 1)
gemm_kernel(const float* __restrict__ bias, float* __restrict__ C, int M) {
    extern __shared__ char smem[];
    const uint32_t sb = smem_u32(smem);
    const int tid = threadIdx.x;
    const int wid = tid >> 5;
    const int lane = tid & 31;

    const int mt = blockIdx.x;
    const int nt = blockIdx.y;
    const int m0 = mt * TILE_M;
    const int n0 = nt * TILE_N;

    if (tid < 32) {
        float4 b4 = *reinterpret_cast<const float4*>(bias + n0 + tid * 4);
        *reinterpret_cast<float4*>(smem + SM_BIAS + tid * 16) = b4;
    }

    const unsigned char* aBase = g_At + (size_t)mt * NKC * A_BLK_BYTES;
    const unsigned char* bBase = g_Bt + (size_t)nt * NKC * B_BLK_BYTES;

    // issue one stage's loads (16KB A + 16KB B = 2048 x16B, 4 per thread)
#define ISSUE_STAGE(kt, buf)                                                          \
    {                                                                                 \
        if ((kt) < NKC) {                                                             \
            const unsigned char* aS = aBase + (size_t)(kt) * A_BLK_BYTES;             \
            const unsigned char* bS = bBase + (size_t)(kt) * B_BLK_BYTES;             \
            _Pragma("unroll")                                                         \
            for (int l = 0; l < 2; ++l) {                                             \
                int off = (tid + l * NTHREADS) * 16;                                  \
                cp_async16(sb + SM_A + (buf) * A_BLK_BYTES + off, aS + off);          \
                cp_async16(sb + SM_B + (buf) * B_BLK_BYTES + off, bS + off);          \
            }                                                                         \
        }                                                                             \
        cp_commit();                                                                  \
    }

    ISSUE_STAGE(0, 0);
    ISSUE_STAGE(1, 1);
    ISSUE_STAGE(2, 2);

    // ---------------- per-warp fragment addressing --------------------------
    const int warp_m = wid >> 2;                      // 0..3
    const int warp_n = wid & 3;                       // 0..3
    const uint32_t sxor = (uint32_t)(lane & 7) * 16;  // SW128 per-row xor
    uint32_t arow[2], brow[2];
#pragma unroll
    for (int mi = 0; mi < 2; ++mi)
        arow[mi] = (uint32_t)((warp_m * 32 + mi * 16 + (lane & 7) + ((lane >> 3) & 1) * 8) << 7);
#pragma unroll
    for (int h = 0; h < 2; ++h)
        brow[h] = (uint32_t)((warp_n * 32 + h * 16 + (lane & 7) + ((lane >> 4) & 1) * 8) << 7);
    const uint32_t acsel = (uint32_t)((lane >> 4) & 1) * 16;  // A k8-sub (bytes)
    const uint32_t bcsel = (uint32_t)((lane >> 3) & 1) * 16;  // B k8-sub (bytes)

    float acc[2][4][4];
#pragma unroll
    for (int mi = 0; mi < 2; ++mi)
#pragma unroll
        for (int nj = 0; nj < 4; ++nj)
#pragma unroll
            for (int r = 0; r < 4; ++r) acc[mi][nj][r] = 0.0f;

    uint32_t af[2][8], bf[2][8];

#define LOAD_FRAGS(ks, AA, BB)                                                        \
    {                                                                                 \
        uint32_t kc_ = (uint32_t)(ks) * 32;                                           \
        _Pragma("unroll")                                                             \
        for (int mi = 0; mi < 2; ++mi) {                                              \
            uint32_t ad = sa + arow[mi] + ((kc_ + acsel) ^ sxor);                     \
            asm volatile("ldmatrix.sync.aligned.m8n8.x4.shared.b16 {%0,%1,%2,%3}, [%4];" \
                : "=r"((AA)[mi*4+0]), "=r"((AA)[mi*4+1]),                             \
                  "=r"((AA)[mi*4+2]), "=r"((AA)[mi*4+3]) : "r"(ad));                  \
        }                                                                             \
        _Pragma("unroll")                                                             \
        for (int h = 0; h < 2; ++h) {                                                 \
            uint32_t bd = sbb + brow[h] + ((kc_ + bcsel) ^ sxor);                     \
            asm volatile("ldmatrix.sync.aligned.m8n8.x4.shared.b16 {%0,%1,%2,%3}, [%4];" \
                : "=r"((BB)[h*4+0]), "=r"((BB)[h*4+1]),                               \
                  "=r"((BB)[h*4+2]), "=r"((BB)[h*4+3]) : "r"(bd));                    \
        }                                                                             \
    }

#define DO_MMA(AA, BB)                                                                \
    _Pragma("unroll")                                                                 \
    for (int mi = 0; mi < 2; ++mi)                                                    \
    { _Pragma("unroll")                                                               \
      for (int nj = 0; nj < 4; ++nj) {                                                \
        asm volatile("mma.sync.aligned.m16n8k16.row.col.f32.f16.f16.f32 "             \
            "{%0,%1,%2,%3}, {%4,%5,%6,%7}, {%8,%9}, {%0,%1,%2,%3};"                   \
            : "+f"(acc[mi][nj][0]), "+f"(acc[mi][nj][1]),                             \
              "+f"(acc[mi][nj][2]), "+f"(acc[mi][nj][3])                              \
            : "r"((AA)[mi*4+0]), "r"((AA)[mi*4+1]),                                   \
              "r"((AA)[mi*4+2]), "r"((AA)[mi*4+3]),                                   \
              "r"((BB)[(nj>>1)*4 + (nj&1)*2 + 0]),                                    \
              "r"((BB)[(nj>>1)*4 + (nj&1)*2 + 1]));                                   \
      } }

    // ---------------- mainloop ---------------------------------------------
    for (int kt = 0; kt < NKC; ++kt) {
        const int buf = kt & (STAGES - 1);
        cp_wait<STAGES - 2>();           // stage kt resident
        __syncthreads();                 // also: everyone done with buf from kt-1
        ISSUE_STAGE(kt + STAGES - 1, (kt + STAGES - 1) & (STAGES - 1));

        const uint32_t sa  = sb + SM_A + buf * A_BLK_BYTES;
        const uint32_t sbb = sb + SM_B + buf * B_BLK_BYTES;

        LOAD_FRAGS(0, af[0], bf[0]);
#pragma unroll
        for (int ks = 0; ks < 4; ++ks) {
            const int cur = ks & 1;
            if (ks < 3) LOAD_FRAGS(ks + 1, af[cur ^ 1], bf[cur ^ 1]);
            DO_MMA(af[cur], bf[cur]);
        }
    }

    // ---------------- epilogue: f16-round, +bias(f16), f32 store ------------
    const float* sBias = reinterpret_cast<const float*>(smem + SM_BIAS);
    const int rq = lane >> 2;
    const int cq = (lane & 3) * 2;
#pragma unroll
    for (int mi = 0; mi < 2; ++mi) {
        const int mrow = m0 + warp_m * 32 + mi * 16 + rq;
        float* out0 = C + (size_t)mrow * N_DIM;
        float* out1 = out0 + (size_t)8 * N_DIM;
#pragma unroll
        for (int nj = 0; nj < 4; ++nj) {
            const int nl = warp_n * 32 + nj * 8 + cq;
            const __half bh0 = __float2half(sBias[nl]);
            const __half bh1 = __float2half(sBias[nl + 1]);
            float2 v0, v1;
            v0.x = __half2float(__hadd(__float2half(acc[mi][nj][0]), bh0));
            v0.y = __half2float(__hadd(__float2half(acc[mi][nj][1]), bh1));
            v1.x = __half2float(__hadd(__float2half(acc[mi][nj][2]), bh0));
            v1.y = __half2float(__hadd(__float2half(acc[mi][nj][3]), bh1));
            *reinterpret_cast<float2*>(out0 + n0 + nl) = v0;
            *reinterpret_cast<float2*>(out1 + n0 + nl) = v1;
        }
    }
}

// ---------------------------------------------------------------------------
extern "C" void kernel_launch(void* const* d_in, const int* in_sizes, int n_in,
                              void* d_out, int out_size) {
    const float* x       = (const float*)d_in[0];
    const int*   qweight = (const int*)d_in[1];
    const int*   qzeros  = (const int*)d_in[2];
    const float* scales  = (const float*)d_in[3];
    const float* bias    = (const float*)d_in[4];
    float*       out     = (float*)d_out;

    const int M = in_sizes[0] / K_DIM;                // 8192

    // 0) convert x -> tiled/swizzled f16
    {
        size_t threads = (size_t)M * (K_DIM / 8);
        convert_a_kernel<<<(unsigned)((threads + 255) / 256), 256>>>(x, M);
    }
    // 1) dequant -> tiled/swizzled f16 W^T
    {
        dim3 g((N_DIM + 255) / 256, K_DIM / 8);
        dequant_kernel<<<g, 256>>>(qweight, qzeros, scales);
    }
    // 2) mma.sync GEMM + bias
    {
        cudaFuncSetAttribute(gemm_kernel, cudaFuncAttributeMaxDynamicSharedMemorySize,
                             SM_TOTAL);
        dim3 grid(M / TILE_M, N_DIM / TILE_N);        // M-fastest: share B tile in L2
        gemm_kernel<<<grid, NTHREADS, SM_TOTAL>>>(bias, out, M);
    }
}

// round 8
// speedup vs baseline: 1.1611x; 1.1611x over previous
#include <cuda_runtime.h>
#include <cuda_fp16.h>
#include <cstdint>

#define K_DIM 4096
#define N_DIM 11008
#define GROUP 128
#define M_MAX 8192

#define TILE_M 128
#define TILE_N 256
#define KCHUNK 64                       // halves per K-chunk (128 bytes = SW128 row)
#define NKC (K_DIM / KCHUNK)            // 64 K-chunks
#define STAGES 4
#define NTHREADS 256

#define A_BLK_BYTES (TILE_M * 128)      // 16384
#define B_BLK_BYTES (TILE_N * 128)      // 32768

#define N_TILES (N_DIM / TILE_N)        // 43
#define M_TILES_MAX (M_MAX / TILE_M)    // 64

// Scratch: pre-tiled, pre-SW128-swizzled operands (device globals = sanctioned scratch)
__device__ unsigned char g_At[(size_t)M_TILES_MAX * NKC * A_BLK_BYTES]; // 64 MB
__device__ unsigned char g_Bt[(size_t)N_TILES   * NKC * B_BLK_BYTES];   // 90 MB

__device__ __forceinline__ uint32_t swz(uint32_t off) {          // SW128 swizzle
    return off ^ ((off >> 3) & 0x70);
}

__device__ __forceinline__ uint32_t smem_u32(const void* p) {
    uint32_t a;
    asm("{ .reg .u64 t; cvta.to.shared.u64 t, %1; cvt.u32.u64 %0, t; }" : "=r"(a) : "l"(p));
    return a;
}
__device__ __forceinline__ void cp_async16(uint32_t smem_dst, const void* gptr) {
    asm volatile("cp.async.cg.shared.global [%0], [%1], 16;\n" :: "r"(smem_dst), "l"(gptr));
}
__device__ __forceinline__ void cp_commit() {
    asm volatile("cp.async.commit_group;\n");
}
template <int Nn>
__device__ __forceinline__ void cp_wait() {
    asm volatile("cp.async.wait_group %0;\n" :: "n"(Nn));
}

// ---------------------------------------------------------------------------
// Kernel 0: convert x f32 -> f16, tiled + swizzled into g_At
// ---------------------------------------------------------------------------
__global__ void convert_a_kernel(const float* __restrict__ x, int M) {
    size_t idx = (size_t)blockIdx.x * blockDim.x + threadIdx.x;
    int k8 = (int)(idx & (K_DIM / 8 - 1));            // 0..511
    int m = (int)(idx >> 9);
    if (m >= M) return;
    const float4* src = reinterpret_cast<const float4*>(x + (size_t)m * K_DIM + k8 * 8);
    float4 v0 = src[0], v1 = src[1];
    __half2 h0 = __floats2half2_rn(v0.x, v0.y);
    __half2 h1 = __floats2half2_rn(v0.z, v0.w);
    __half2 h2 = __floats2half2_rn(v1.x, v1.y);
    __half2 h3 = __floats2half2_rn(v1.z, v1.w);
    uint4 pack;
    pack.x = *reinterpret_cast<uint32_t*>(&h0);
    pack.y = *reinterpret_cast<uint32_t*>(&h1);
    pack.z = *reinterpret_cast<uint32_t*>(&h2);
    pack.w = *reinterpret_cast<uint32_t*>(&h3);
    int k0 = k8 * 8;
    int mt = m >> 7, r = m & 127, kc = k0 >> 6, c0 = k0 & 63;
    size_t off = ((size_t)mt * NKC + kc) * A_BLK_BYTES + swz((uint32_t)(r * 128 + c0 * 2));
    *reinterpret_cast<uint4*>(g_At + off) = pack;
}

// ---------------------------------------------------------------------------
// Kernel 1: GPTQ int4 dequant -> f16 W^T [N,K], tiled + swizzled into g_Bt
// ---------------------------------------------------------------------------
__global__ void dequant_kernel(const int* __restrict__ qweight,
                               const int* __restrict__ qzeros,
                               const float* __restrict__ scales) {
    int n = blockIdx.x * blockDim.x + threadIdx.x;
    int i = blockIdx.y;                               // 0..K/8-1
    if (n >= N_DIM) return;

    int q = qweight[(size_t)i * N_DIM + n];
    int k0 = i * 8;
    int g = i >> 4;                                   // k0 / GROUP
    int zpack = qzeros[g * (N_DIM / 8) + (n >> 3)];
    float zf = (float)(((zpack >> ((n & 7) * 4)) & 15) + 1);
    float s = scales[(size_t)g * N_DIM + n];

    union { __half h[8]; uint4 v; } u;                // 16B-aligned pack
#pragma unroll
    for (int j = 0; j < 8; ++j)
        u.h[j] = __float2half(((float)((q >> (4 * j)) & 15) - zf) * s);

    int nt = n / TILE_N, r = n % TILE_N, kc = k0 >> 6, c0 = k0 & 63;
    size_t off = ((size_t)nt * NKC + kc) * B_BLK_BYTES + swz((uint32_t)(r * 128 + c0 * 2));
    *reinterpret_cast<uint4*>(g_Bt + off) = u.v;
}

// ---------------------------------------------------------------------------
// Kernel 2: mma.sync GEMM  C[M,N] = A * B^T + bias  (f32 out)
// 256 threads, 8 warps (2x4), each warp 64(M) x 64(N).
// 4-stage cp.async pipeline, one __syncthreads per K-chunk.
// ---------------------------------------------------------------------------
#define SM_BIAS   0                                  // 256 f32 = 1KB
#define SM_A      1024                               // 4 x 16KB
#define SM_B      (SM_A + STAGES * A_BLK_BYTES)      // 4 x 32KB
#define SM_TOTAL  (SM_B + STAGES * B_BLK_BYTES)      // 197632 B

__global__ void __launch_bounds__(NTHREADS, 1)
gemm_kernel(const float* __restrict__ bias, float* __restrict__ C, int M) {
    extern __shared__ char smem[];
    const uint32_t sb = smem_u32(smem);
    const int tid = threadIdx.x;
    const int wid = tid >> 5;
    const int lane = tid & 31;

    const int mt = blockIdx.x;
    const int nt = blockIdx.y;
    const int m0 = mt * TILE_M;
    const int n0 = nt * TILE_N;

    if (tid < 64) {
        float4 b4 = *reinterpret_cast<const float4*>(bias + n0 + tid * 4);
        *reinterpret_cast<float4*>(smem + SM_BIAS + tid * 16) = b4;
    }

    const unsigned char* aBase = g_At + (size_t)mt * NKC * A_BLK_BYTES;
    const unsigned char* bBase = g_Bt + (size_t)nt * NKC * B_BLK_BYTES;

    // issue one stage's loads (16KB A + 32KB B = 3072 x16B, 12 per thread)
#define ISSUE_STAGE(kt, buf)                                                          \
    {                                                                                 \
        if ((kt) < NKC) {                                                             \
            const unsigned char* aS = aBase + (size_t)(kt) * A_BLK_BYTES;             \
            const unsigned char* bS = bBase + (size_t)(kt) * B_BLK_BYTES;             \
            _Pragma("unroll")                                                         \
            for (int l = 0; l < 4; ++l) {                                             \
                int off = (tid + l * NTHREADS) * 16;                                  \
                cp_async16(sb + SM_A + (buf) * A_BLK_BYTES + off, aS + off);          \
            }                                                                         \
            _Pragma("unroll")                                                         \
            for (int l = 0; l < 8; ++l) {                                             \
                int off = (tid + l * NTHREADS) * 16;                                  \
                cp_async16(sb + SM_B + (buf) * B_BLK_BYTES + off, bS + off);          \
            }                                                                         \
        }                                                                             \
        cp_commit();                                                                  \
    }

    ISSUE_STAGE(0, 0);
    ISSUE_STAGE(1, 1);
    ISSUE_STAGE(2, 2);

    // ---------------- per-warp fragment addressing --------------------------
    const int warp_m = wid >> 2;                      // 0..1 (64 M-rows)
    const int warp_n = wid & 3;                       // 0..3 (64 N-cols)
    const uint32_t sxor = (uint32_t)(lane & 7) * 16;  // SW128 per-row xor
    uint32_t arow[4], brow[4];
#pragma unroll
    for (int mi = 0; mi < 4; ++mi)
        arow[mi] = (uint32_t)((warp_m * 64 + mi * 16 + (lane & 7) + ((lane >> 3) & 1) * 8) << 7);
#pragma unroll
    for (int h = 0; h < 4; ++h)
        brow[h] = (uint32_t)((warp_n * 64 + h * 16 + (lane & 7) + ((lane >> 4) & 1) * 8) << 7);
    const uint32_t acsel = (uint32_t)((lane >> 4) & 1) * 16;  // A k8-sub (bytes)
    const uint32_t bcsel = (uint32_t)((lane >> 3) & 1) * 16;  // B k8-sub (bytes)

    float acc[4][8][4];
#pragma unroll
    for (int mi = 0; mi < 4; ++mi)
#pragma unroll
        for (int nj = 0; nj < 8; ++nj)
#pragma unroll
            for (int r = 0; r < 4; ++r) acc[mi][nj][r] = 0.0f;

    uint32_t af[2][16], bf[2][16];

#define LOAD_FRAGS(ks, AA, BB)                                                        \
    {                                                                                 \
        uint32_t kc_ = (uint32_t)(ks) * 32;                                           \
        _Pragma("unroll")                                                             \
        for (int mi = 0; mi < 4; ++mi) {                                              \
            uint32_t ad = sa + arow[mi] + ((kc_ + acsel) ^ sxor);                     \
            asm volatile("ldmatrix.sync.aligned.m8n8.x4.shared.b16 {%0,%1,%2,%3}, [%4];" \
                : "=r"((AA)[mi*4+0]), "=r"((AA)[mi*4+1]),                             \
                  "=r"((AA)[mi*4+2]), "=r"((AA)[mi*4+3]) : "r"(ad));                  \
        }                                                                             \
        _Pragma("unroll")                                                             \
        for (int h = 0; h < 4; ++h) {                                                 \
            uint32_t bd = sbb + brow[h] + ((kc_ + bcsel) ^ sxor);                     \
            asm volatile("ldmatrix.sync.aligned.m8n8.x4.shared.b16 {%0,%1,%2,%3}, [%4];" \
                : "=r"((BB)[h*4+0]), "=r"((BB)[h*4+1]),                               \
                  "=r"((BB)[h*4+2]), "=r"((BB)[h*4+3]) : "r"(bd));                    \
        }                                                                             \
    }

#define DO_MMA(AA, BB)                                                                \
    _Pragma("unroll")                                                                 \
    for (int mi = 0; mi < 4; ++mi)                                                    \
    { _Pragma("unroll")                                                               \
      for (int nj = 0; nj < 8; ++nj) {                                                \
        asm volatile("mma.sync.aligned.m16n8k16.row.col.f32.f16.f16.f32 "             \
            "{%0,%1,%2,%3}, {%4,%5,%6,%7}, {%8,%9}, {%0,%1,%2,%3};"                   \
            : "+f"(acc[mi][nj][0]), "+f"(acc[mi][nj][1]),                             \
              "+f"(acc[mi][nj][2]), "+f"(acc[mi][nj][3])                              \
            : "r"((AA)[mi*4+0]), "r"((AA)[mi*4+1]),                                   \
              "r"((AA)[mi*4+2]), "r"((AA)[mi*4+3]),                                   \
              "r"((BB)[(nj>>1)*4 + (nj&1)*2 + 0]),                                    \
              "r"((BB)[(nj>>1)*4 + (nj&1)*2 + 1]));                                   \
      } }

    // ---------------- mainloop ---------------------------------------------
    for (int kt = 0; kt < NKC; ++kt) {
        const int buf = kt & (STAGES - 1);
        cp_wait<STAGES - 2>();           // stage kt resident
        __syncthreads();                 // also: everyone done with buf from kt-1
        ISSUE_STAGE(kt + STAGES - 1, (kt + STAGES - 1) & (STAGES - 1));

        const uint32_t sa  = sb + SM_A + buf * A_BLK_BYTES;
        const uint32_t sbb = sb + SM_B + buf * B_BLK_BYTES;

        LOAD_FRAGS(0, af[0], bf[0]);
#pragma unroll
        for (int ks = 0; ks < 4; ++ks) {
            const int cur = ks & 1;
            if (ks < 3) LOAD_FRAGS(ks + 1, af[cur ^ 1], bf[cur ^ 1]);
            DO_MMA(af[cur], bf[cur]);
        }
    }

    // ---------------- epilogue: f16-round, +bias(f16), f32 store ------------
    const float* sBias = reinterpret_cast<const float*>(smem + SM_BIAS);
    const int rq = lane >> 2;
    const int cq = (lane & 3) * 2;
#pragma unroll
    for (int mi = 0; mi < 4; ++mi) {
        const int mrow = m0 + warp_m * 64 + mi * 16 + rq;
        float* out0 = C + (size_t)mrow * N_DIM;
        float* out1 = out0 + (size_t)8 * N_DIM;
#pragma unroll
        for (int nj = 0; nj < 8; ++nj) {
            const int nl = warp_n * 64 + nj * 8 + cq;
            const __half bh0 = __float2half(sBias[nl]);
            const __half bh1 = __float2half(sBias[nl + 1]);
            float2 v0, v1;
            v0.x = __half2float(__hadd(__float2half(acc[mi][nj][0]), bh0));
            v0.y = __half2float(__hadd(__float2half(acc[mi][nj][1]), bh1));
            v1.x = __half2float(__hadd(__float2half(acc[mi][nj][2]), bh0));
            v1.y = __half2float(__hadd(__float2half(acc[mi][nj][3]), bh1));
            *reinterpret_cast<float2*>(out0 + n0 + nl) = v0;
            *reinterpret_cast<float2*>(out1 + n0 + nl) = v1;
        }
    }
}

// ---------------------------------------------------------------------------
extern "C" void kernel_launch(void* const* d_in, const int* in_sizes, int n_in,
                              void* d_out, int out_size) {
    const float* x       = (const float*)d_in[0];
    const int*   qweight = (const int*)d_in[1];
    const int*   qzeros  = (const int*)d_in[2];
    const float* scales  = (const float*)d_in[3];
    const float* bias    = (const float*)d_in[4];
    float*       out     = (float*)d_out;

    const int M = in_sizes[0] / K_DIM;                // 8192

    // 0) convert x -> tiled/swizzled f16
    {
        size_t threads = (size_t)M * (K_DIM / 8);
        convert_a_kernel<<<(unsigned)((threads + 255) / 256), 256>>>(x, M);
    }
    // 1) dequant -> tiled/swizzled f16 W^T
    {
        dim3 g((N_DIM + 255) / 256, K_DIM / 8);
        dequant_kernel<<<g, 256>>>(qweight, qzeros, scales);
    }
    // 2) mma.sync GEMM + bias
    {
        cudaFuncSetAttribute(gemm_kernel, cudaFuncAttributeMaxDynamicSharedMemorySize,
                             SM_TOTAL);
        dim3 grid(M / TILE_M, N_DIM / TILE_N);        // M-fastest: share B tile in L2
        gemm_kernel<<<grid, NTHREADS, SM_TOTAL>>>(bias, out, M);
    }
}

// round 10
// speedup vs baseline: 1.2597x; 1.0848x over previous
#include <cuda_runtime.h>
#include <cuda_fp16.h>
#include <cstdint>

#define K_DIM 4096
#define N_DIM 11008
#define GROUP 128
#define M_MAX 8192

#define TILE_M 128
#define TILE_N 256
#define KCHUNK 64                       // halves per K-chunk (128 bytes = SW128 row)
#define NKC (K_DIM / KCHUNK)            // 64 K-chunks
#define STAGES 4
#define NTHREADS 256

#define A_BLK_BYTES (TILE_M * 128)      // 16384
#define B_BLK_BYTES (TILE_N * 128)      // 32768

#define N_TILES (N_DIM / TILE_N)        // 43
#define M_TILES_MAX (M_MAX / TILE_M)    // 64

// Scratch: pre-tiled, pre-SW128-swizzled operands (device globals = sanctioned scratch)
__device__ unsigned char g_At[(size_t)M_TILES_MAX * NKC * A_BLK_BYTES]; // 64 MB
__device__ unsigned char g_Bt[(size_t)N_TILES   * NKC * B_BLK_BYTES];   // 90 MB

__device__ __forceinline__ uint32_t swz(uint32_t off) {          // SW128 swizzle
    return off ^ ((off >> 3) & 0x70);
}

__device__ __forceinline__ uint32_t smem_u32(const void* p) {
    uint32_t a;
    asm("{ .reg .u64 t; cvta.to.shared.u64 t, %1; cvt.u32.u64 %0, t; }" : "=r"(a) : "l"(p));
    return a;
}
__device__ __forceinline__ void cp_async16(uint32_t smem_dst, const void* gptr) {
    asm volatile("cp.async.cg.shared.global [%0], [%1], 16;\n" :: "r"(smem_dst), "l"(gptr));
}
__device__ __forceinline__ void cp_commit() {
    asm volatile("cp.async.commit_group;\n");
}
template <int Nn>
__device__ __forceinline__ void cp_wait() {
    asm volatile("cp.async.wait_group %0;\n" :: "n"(Nn));
}

// ---------------------------------------------------------------------------
// Kernel 0: merged prep.
//   idx <  M*K/8          : convert x f32->f16, tiled+swizzled into g_At
//   idx >= M*K/8          : GPTQ int4 dequant -> f16 W^T tiled+swizzled g_Bt
// ---------------------------------------------------------------------------
__global__ void prep_kernel(const float* __restrict__ x,
                            const int* __restrict__ qweight,
                            const int* __restrict__ qzeros,
                            const float* __restrict__ scales,
                            int M) {
    size_t idx = (size_t)blockIdx.x * blockDim.x + threadIdx.x;
    const size_t a_work = (size_t)M * (K_DIM / 8);

    if (idx < a_work) {
        int k8 = (int)(idx & (K_DIM / 8 - 1));        // 0..511
        int m = (int)(idx >> 9);
        const float4* src = reinterpret_cast<const float4*>(x + (size_t)m * K_DIM + k8 * 8);
        float4 v0 = src[0], v1 = src[1];
        __half2 h0 = __floats2half2_rn(v0.x, v0.y);
        __half2 h1 = __floats2half2_rn(v0.z, v0.w);
        __half2 h2 = __floats2half2_rn(v1.x, v1.y);
        __half2 h3 = __floats2half2_rn(v1.z, v1.w);
        uint4 pack;
        pack.x = *reinterpret_cast<uint32_t*>(&h0);
        pack.y = *reinterpret_cast<uint32_t*>(&h1);
        pack.z = *reinterpret_cast<uint32_t*>(&h2);
        pack.w = *reinterpret_cast<uint32_t*>(&h3);
        int k0 = k8 * 8;
        int mt = m >> 7, r = m & 127, kc = k0 >> 6, c0 = k0 & 63;
        size_t off = ((size_t)mt * NKC + kc) * A_BLK_BYTES + swz((uint32_t)(r * 128 + c0 * 2));
        *reinterpret_cast<uint4*>(g_At + off) = pack;
    } else {
        size_t j = idx - a_work;
        if (j >= (size_t)(K_DIM / 8) * N_DIM) return;
        int i = (int)(j / N_DIM);                     // 0..511 packed-K row
        int n = (int)(j % N_DIM);

        int q = qweight[(size_t)i * N_DIM + n];
        int k0 = i * 8;
        int g = i >> 4;                               // k0 / GROUP
        int zpack = qzeros[g * (N_DIM / 8) + (n >> 3)];
        float zf = (float)(((zpack >> ((n & 7) * 4)) & 15) + 1);
        float s = scales[(size_t)g * N_DIM + n];

        union { __half h[8]; uint4 v; } u;            // 16B-aligned pack
#pragma unroll
        for (int jj = 0; jj < 8; ++jj)
            u.h[jj] = __float2half(((float)((q >> (4 * jj)) & 15) - zf) * s);

        int nt = n / TILE_N, r = n % TILE_N, kc = k0 >> 6, c0 = k0 & 63;
        size_t off = ((size_t)nt * NKC + kc) * B_BLK_BYTES + swz((uint32_t)(r * 128 + c0 * 2));
        *reinterpret_cast<uint4*>(g_Bt + off) = u.v;
    }
}

// ---------------------------------------------------------------------------
// Kernel 1: mma.sync GEMM  C[M,N] = A * B^T + bias  (f32 out)
// 256 threads, 8 warps (2x4), each warp 64(M) x 64(N).
// 4-stage cp.async pipeline; stage-feed LDGSTS spread across the ks loop so
// the tensor pipe never stalls behind LSU issue at chunk heads.
// ---------------------------------------------------------------------------
#define SM_BIAS   0                                  // 256 f32 = 1KB
#define SM_A      1024                               // 4 x 16KB
#define SM_B      (SM_A + STAGES * A_BLK_BYTES)      // 4 x 32KB
#define SM_TOTAL  (SM_B + STAGES * B_BLK_BYTES)      // 197632 B

__global__ void __launch_bounds__(NTHREADS, 1)
gemm_kernel(const float* __restrict__ bias, float* __restrict__ C, int M) {
    extern __shared__ char smem[];
    const uint32_t sb = smem_u32(smem);
    const int tid = threadIdx.x;
    const int wid = tid >> 5;
    const int lane = tid & 31;

    const int mt = blockIdx.x;
    const int nt = blockIdx.y;
    const int m0 = mt * TILE_M;
    const int n0 = nt * TILE_N;

    if (tid < 64) {
        float4 b4 = *reinterpret_cast<const float4*>(bias + n0 + tid * 4);
        *reinterpret_cast<float4*>(smem + SM_BIAS + tid * 16) = b4;
    }

    const unsigned char* aBase = g_At + (size_t)mt * NKC * A_BLK_BYTES;
    const unsigned char* bBase = g_Bt + (size_t)nt * NKC * B_BLK_BYTES;

    // full-stage issue (pipeline fill only): 16KB A + 32KB B
#define ISSUE_STAGE(kt, buf)                                                          \
    {                                                                                 \
        if ((kt) < NKC) {                                                             \
            const unsigned char* aS = aBase + (size_t)(kt) * A_BLK_BYTES;             \
            const unsigned char* bS = bBase + (size_t)(kt) * B_BLK_BYTES;             \
            _Pragma("unroll")                                                         \
            for (int l = 0; l < 4; ++l) {                                             \
                int off = (tid + l * NTHREADS) * 16;                                  \
                cp_async16(sb + SM_A + (buf) * A_BLK_BYTES + off, aS + off);          \
            }                                                                         \
            _Pragma("unroll")                                                         \
            for (int l = 0; l < 8; ++l) {                                             \
                int off = (tid + l * NTHREADS) * 16;                                  \
                cp_async16(sb + SM_B + (buf) * B_BLK_BYTES + off, bS + off);          \
            }                                                                         \
        }                                                                             \
        cp_commit();                                                                  \
    }

    // quarter-stage issue: part p of 4 (1 A-slice + 2 B-slices = 3 LDGSTS)
#define ISSUE_PART(ktn, bufv, part)                                                   \
    {                                                                                 \
        if ((ktn) < NKC) {                                                            \
            const unsigned char* aS = aBase + (size_t)(ktn) * A_BLK_BYTES;            \
            const unsigned char* bS = bBase + (size_t)(ktn) * B_BLK_BYTES;            \
            int offa = (tid + (part) * NTHREADS) * 16;                                \
            cp_async16(sb + SM_A + (bufv) * A_BLK_BYTES + offa, aS + offa);           \
            int offb = (tid + (2 * (part)) * NTHREADS) * 16;                          \
            cp_async16(sb + SM_B + (bufv) * B_BLK_BYTES + offb, bS + offb);           \
            offb += NTHREADS * 16;                                                    \
            cp_async16(sb + SM_B + (bufv) * B_BLK_BYTES + offb, bS + offb);           \
        }                                                                             \
    }

    ISSUE_STAGE(0, 0);
    ISSUE_STAGE(1, 1);
    ISSUE_STAGE(2, 2);

    // ---------------- per-warp fragment addressing --------------------------
    const int warp_m = wid >> 2;                      // 0..1 (64 M-rows)
    const int warp_n = wid & 3;                       // 0..3 (64 N-cols)
    const uint32_t sxor = (uint32_t)(lane & 7) * 16;  // SW128 per-row xor
    uint32_t arow[4], brow[4];
#pragma unroll
    for (int mi = 0; mi < 4; ++mi)
        arow[mi] = (uint32_t)((warp_m * 64 + mi * 16 + (lane & 7) + ((lane >> 3) & 1) * 8) << 7);
#pragma unroll
    for (int h = 0; h < 4; ++h)
        brow[h] = (uint32_t)((warp_n * 64 + h * 16 + (lane & 7) + ((lane >> 4) & 1) * 8) << 7);
    const uint32_t acsel = (uint32_t)((lane >> 4) & 1) * 16;  // A k8-sub (bytes)
    const uint32_t bcsel = (uint32_t)((lane >> 3) & 1) * 16;  // B k8-sub (bytes)

    float acc[4][8][4];
#pragma unroll
    for (int mi = 0; mi < 4; ++mi)
#pragma unroll
        for (int nj = 0; nj < 8; ++nj)
#pragma unroll
            for (int r = 0; r < 4; ++r) acc[mi][nj][r] = 0.0f;

    uint32_t af[2][16], bf[2][16];

#define LOAD_FRAGS(ks, AA, BB)                                                        \
    {                                                                                 \
        uint32_t kc_ = (uint32_t)(ks) * 32;                                           \
        _Pragma("unroll")                                                             \
        for (int mi = 0; mi < 4; ++mi) {                                              \
            uint32_t ad = sa + arow[mi] + ((kc_ + acsel) ^ sxor);                     \
            asm volatile("ldmatrix.sync.aligned.m8n8.x4.shared.b16 {%0,%1,%2,%3}, [%4];" \
                : "=r"((AA)[mi*4+0]), "=r"((AA)[mi*4+1]),                             \
                  "=r"((AA)[mi*4+2]), "=r"((AA)[mi*4+3]) : "r"(ad));                  \
        }                                                                             \
        _Pragma("unroll")                                                             \
        for (int h = 0; h < 4; ++h) {                                                 \
            uint32_t bd = sbb + brow[h] + ((kc_ + bcsel) ^ sxor);                     \
            asm volatile("ldmatrix.sync.aligned.m8n8.x4.shared.b16 {%0,%1,%2,%3}, [%4];" \
                : "=r"((BB)[h*4+0]), "=r"((BB)[h*4+1]),                               \
                  "=r"((BB)[h*4+2]), "=r"((BB)[h*4+3]) : "r"(bd));                    \
        }                                                                             \
    }

#define DO_MMA(AA, BB)                                                                \
    _Pragma("unroll")                                                                 \
    for (int mi = 0; mi < 4; ++mi)                                                    \
    { _Pragma("unroll")                                                               \
      for (int nj = 0; nj < 8; ++nj) {                                                \
        asm volatile("mma.sync.aligned.m16n8k16.row.col.f32.f16.f16.f32 "             \
            "{%0,%1,%2,%3}, {%4,%5,%6,%7}, {%8,%9}, {%0,%1,%2,%3};"                   \
            : "+f"(acc[mi][nj][0]), "+f"(acc[mi][nj][1]),                             \
              "+f"(acc[mi][nj][2]), "+f"(acc[mi][nj][3])                              \
            : "r"((AA)[mi*4+0]), "r"((AA)[mi*4+1]),                                   \
              "r"((AA)[mi*4+2]), "r"((AA)[mi*4+3]),                                   \
              "r"((BB)[(nj>>1)*4 + (nj&1)*2 + 0]),                                    \
              "r"((BB)[(nj>>1)*4 + (nj&1)*2 + 1]));                                   \
      } }

    // ---------------- mainloop ---------------------------------------------
    for (int kt = 0; kt < NKC; ++kt) {
        const int buf = kt & (STAGES - 1);
        cp_wait<STAGES - 2>();           // stage kt resident
        __syncthreads();                 // everyone done with buf from kt-1

        const uint32_t sa  = sb + SM_A + buf * A_BLK_BYTES;
        const uint32_t sbb = sb + SM_B + buf * B_BLK_BYTES;
        const int ktn  = kt + STAGES - 1;
        const int bufn = ktn & (STAGES - 1);

        LOAD_FRAGS(0, af[0], bf[0]);
#pragma unroll
        for (int ks = 0; ks < 4; ++ks) {
            const int cur = ks & 1;
            if (ks < 3) LOAD_FRAGS(ks + 1, af[cur ^ 1], bf[cur ^ 1]);
            ISSUE_PART(ktn, bufn, ks);   // 3 LDGSTS hidden under the HMMA burst
            if (ks == 3) cp_commit();
            DO_MMA(af[cur], bf[cur]);
        }
    }

    // ---------------- epilogue: f16-round, +bias(f16), f32 store ------------
    const float* sBias = reinterpret_cast<const float*>(smem + SM_BIAS);
    const int rq = lane >> 2;
    const int cq = (lane & 3) * 2;
#pragma unroll
    for (int mi = 0; mi < 4; ++mi) {
        const int mrow = m0 + warp_m * 64 + mi * 16 + rq;
        float* out0 = C + (size_t)mrow * N_DIM;
        float* out1 = out0 + (size_t)8 * N_DIM;
#pragma unroll
        for (int nj = 0; nj < 8; ++nj) {
            const int nl = warp_n * 64 + nj * 8 + cq;
            const __half bh0 = __float2half(sBias[nl]);
            const __half bh1 = __float2half(sBias[nl + 1]);
            float2 v0, v1;
            v0.x = __half2float(__hadd(__float2half(acc[mi][nj][0]), bh0));
            v0.y = __half2float(__hadd(__float2half(acc[mi][nj][1]), bh1));
            v1.x = __half2float(__hadd(__float2half(acc[mi][nj][2]), bh0));
            v1.y = __half2float(__hadd(__float2half(acc[mi][nj][3]), bh1));
            *reinterpret_cast<float2*>(out0 + n0 + nl) = v0;
            *reinterpret_cast<float2*>(out1 + n0 + nl) = v1;
        }
    }
}

// ---------------------------------------------------------------------------
extern "C" void kernel_launch(void* const* d_in, const int* in_sizes, int n_in,
                              void* d_out, int out_size) {
    const float* x       = (const float*)d_in[0];
    const int*   qweight = (const int*)d_in[1];
    const int*   qzeros  = (const int*)d_in[2];
    const float* scales  = (const float*)d_in[3];
    const float* bias    = (const float*)d_in[4];
    float*       out     = (float*)d_out;

    const int M = in_sizes[0] / K_DIM;                // 8192

    // 0) merged prep: convert x + dequant W
    {
        size_t total = (size_t)M * (K_DIM / 8) + (size_t)(K_DIM / 8) * N_DIM;
        prep_kernel<<<(unsigned)((total + 255) / 256), 256>>>(x, qweight, qzeros, scales, M);
    }
    // 1) mma.sync GEMM + bias
    {
        cudaFuncSetAttribute(gemm_kernel, cudaFuncAttributeMaxDynamicSharedMemorySize,
                             SM_TOTAL);
        dim3 grid(M / TILE_M, N_DIM / TILE_N);        // M-fastest: share B tile in L2
        gemm_kernel<<<grid, NTHREADS, SM_TOTAL>>>(bias, out, M);
    }
}